// round 4
// baseline (speedup 1.0000x reference)
#include <cuda_runtime.h>
#include <cstdint>
#include <cstddef>

#define HID     64
#define DIMH    128
#define DIMU    256
#define ROWS    8      // rows per CTA
#define THREADS 128
#define NWARP   4
#define JPW     8      // j-columns per jgroup; 16 groups x 8 = 128 j
#define WPAD    132

// Aligned, repacked weights + params (written by prep_kernel each launch).
__device__ float g_Wpack[128 * 128];   // rows 0..63: W1u[:,1:]; rows 64..127: W1p[:,2:]
__device__ float g_par[7 * 64 + 2];
// par layout: [0,64) cu | [64,128) cp0 | [128,192) cp1 | [192,256) b1u
//             [256,320) b1p | [320,384) W2u | [384,448) W2p | [448] b2u | [449] b2p

__device__ __forceinline__ float gelu_f(float x) {
  return 0.5f * x * (1.0f + erff(x * 0.7071067811865476f));
}

__global__ void __launch_bounds__(THREADS) prep_kernel(
    const float* __restrict__ W1u, const float* __restrict__ b1u,
    const float* __restrict__ W2u, const float* __restrict__ b2u,
    const float* __restrict__ W1p, const float* __restrict__ b1p,
    const float* __restrict__ W2p, const float* __restrict__ b2p)
{
  int t = threadIdx.x;          // 0..127 = k column
  int b = blockIdx.x;           // 16 blocks, 8 rows each
#pragma unroll
  for (int rr = 0; rr < 8; rr++) {
    int r = b * 8 + rr;
    float v = (r < HID) ? W1u[r * 129 + 1 + t]
                        : W1p[(r - HID) * 130 + 2 + t];
    g_Wpack[r * 128 + t] = v;
  }
  if (b == 0 && t < HID) {
    g_par[t]        = W1u[t * 129];      // cu
    g_par[64 + t]   = W1p[t * 130];      // cp0
    g_par[128 + t]  = W1p[t * 130 + 1];  // cp1
    g_par[192 + t]  = b1u[t];
    g_par[256 + t]  = b1p[t];
    g_par[320 + t]  = W2u[t];
    g_par[384 + t]  = W2p[t];
    if (t == 0) { g_par[448] = b2u[0]; g_par[449] = b2p[0]; }
  }
}

__global__ void __launch_bounds__(THREADS) fem_main(
    const float* __restrict__ u, const float* __restrict__ h,
    float* __restrict__ out)
{
  __shared__ float hs[ROWS][WPAD];
  __shared__ float cn1[ROWS], c01s[ROWS], c10s[ROWS], c11s[ROWS];
  __shared__ float partial[16][ROWS];

  const int tid  = threadIdx.x;
  const int lane = tid & 31;
  const int w    = tid >> 5;
  const int r0   = blockIdx.x * ROWS;

  // ---- stage h tile [8 x 128]: 2 float4 per thread, coalesced ----
  {
    const float4* h4 = reinterpret_cast<const float4*>(h) + (size_t)r0 * (DIMH / 4);
#pragma unroll
    for (int it = 0; it < 2; it++) {
      int i = tid + it * THREADS;            // 0..255
      float4 v = h4[i];
      int row = i >> 5, c4 = i & 31;
      *reinterpret_cast<float4*>(&hs[row][c4 * 4]) = v;
    }
  }

  // ---- count u bits: warp w handles rows w and w+4 ----
  {
    const float4* u4 = reinterpret_cast<const float4*>(u);
#pragma unroll
    for (int t2 = 0; t2 < 2; t2++) {
      int rr = w + t2 * NWARP;
      size_t base = (size_t)(r0 + rr) * (DIMU / 4);
      float4 a = u4[base + lane];
      float4 b = u4[base + 32 + lane];
      int a0 = a.x > 0.5f, a1 = a.y > 0.5f, a2 = a.z > 0.5f, a3 = a.w > 0.5f;
      int e0 = b.x > 0.5f, e1 = b.y > 0.5f, e2 = b.z > 0.5f, e3 = b.w > 0.5f;
      int n1 = a0 + a1 + a2 + a3 + e0 + e1 + e2 + e3;
      const unsigned F = 0xffffffffu;
      int a0n  = __shfl_down_sync(F, a0, 1);
      int e0n  = __shfl_down_sync(F, e0, 1);
      int e0l0 = __shfl_sync(F, e0, 0);
      int c11 = 0, c10 = 0, c01 = 0;
#define ADDP(X, Y) { c11 += (X) & (Y); c10 += (X) & (1 ^ (Y)); c01 += (1 ^ (X)) & (Y); }
      ADDP(a0, a1) ADDP(a1, a2) ADDP(a2, a3)
      int xa = (lane < 31) ? a0n : e0l0;
      ADDP(a3, xa)
      ADDP(e0, e1) ADDP(e1, e2) ADDP(e2, e3)
      if (lane < 31) ADDP(e3, e0n)
#undef ADDP
      n1  = __reduce_add_sync(F, n1);
      c11 = __reduce_add_sync(F, c11);
      c10 = __reduce_add_sync(F, c10);
      c01 = __reduce_add_sync(F, c01);
      if (lane == 0) {
        cn1[rr]  = (float)n1;
        c11s[rr] = (float)c11;
        c10s[rr] = (float)c10;
        c01s[rr] = (float)c01;
      }
    }
  }
  __syncthreads();

  // ---- fused GEMM ----
  // row = lane&7 (4 replicas per warp); jgroup g = 4w + (lane>>3) -> 16 groups.
  // W read straight from g_Wpack via quarter-warp-uniform LDG.128 (L1-hot).
  const int row   = lane & 7;
  const int g     = (w << 2) + (lane >> 3);
  const int jbase = g * JPW;
  unsigned long long acc2[JPW];
#pragma unroll
  for (int jj = 0; jj < JPW; jj++) acc2[jj] = 0ull;
  const float* hrow = hs[row];
  const float* __restrict__ wrow = g_Wpack + jbase * 128;
#pragma unroll 2
  for (int k = 0; k < DIMH; k += 4) {
    ulonglong2 hv = *reinterpret_cast<const ulonglong2*>(hrow + k);
#pragma unroll
    for (int jj = 0; jj < JPW; jj++) {
      ulonglong2 wv = *reinterpret_cast<const ulonglong2*>(wrow + jj * 128 + k);
      asm("fma.rn.f32x2 %0, %1, %2, %0;" : "+l"(acc2[jj]) : "l"(hv.x), "l"(wv.x));
      asm("fma.rn.f32x2 %0, %1, %2, %0;" : "+l"(acc2[jj]) : "l"(hv.y), "l"(wv.y));
    }
  }

  // ---- epilogue: warps 0-1 unary (g 0..7), warps 2-3 pairwise (g 8..15) ----
  float n1  = cn1[row];
  float c01 = c01s[row];
  float c10 = c10s[row];
  float c11 = c11s[row];
  float val;
  if (w < 2) {
    float g0 = 0.f, g1 = 0.f;
#pragma unroll
    for (int jj = 0; jj < JPW; jj++) {
      int j = jbase + jj;
      float lo, hi;
      asm("mov.b64 {%0, %1}, %2;" : "=f"(lo), "=f"(hi) : "l"(acc2[jj]));
      float base = lo + hi + g_par[192 + j];
      float w2 = g_par[320 + j];
      g0 += w2 * gelu_f(base);
      g1 += w2 * gelu_f(base + g_par[j]);
    }
    val = (256.0f - n1) * g0 + n1 * g1;
  } else {
    float p00 = 0.f, p01 = 0.f, p10 = 0.f, p11 = 0.f;
#pragma unroll
    for (int jj = 0; jj < JPW; jj++) {
      int j = jbase - HID + jj;
      float lo, hi;
      asm("mov.b64 {%0, %1}, %2;" : "=f"(lo), "=f"(hi) : "l"(acc2[jj]));
      float base = lo + hi + g_par[256 + j];
      float A  = g_par[64 + j];
      float Bv = g_par[128 + j];
      float w2 = g_par[384 + j];
      p00 += w2 * gelu_f(base);
      p01 += w2 * gelu_f(base + Bv);
      p10 += w2 * gelu_f(base + A);
      p11 += w2 * gelu_f(base + A + Bv);
    }
    float c00 = 255.0f - c01 - c10 - c11;
    val = c00 * p00 + c01 * p01 + c10 * p10 + c11 * p11;
  }
  partial[g][row] = val;
  __syncthreads();

  if (tid < ROWS) {
    float e = 0.f;
#pragma unroll
    for (int gg = 0; gg < 16; gg++) e += partial[gg][tid];
    e += 256.0f * g_par[448] + 255.0f * g_par[449];
    out[r0 + tid] = e;
  }
}

extern "C" void kernel_launch(void* const* d_in, const int* in_sizes, int n_in,
                              void* d_out, int out_size) {
  const float* u   = (const float*)d_in[0];
  const float* h   = (const float*)d_in[1];
  const float* W1u = (const float*)d_in[2];
  const float* b1u = (const float*)d_in[3];
  const float* W2u = (const float*)d_in[4];
  const float* b2u = (const float*)d_in[5];
  const float* W1p = (const float*)d_in[6];
  const float* b1p = (const float*)d_in[7];
  const float* W2p = (const float*)d_in[8];
  const float* b2p = (const float*)d_in[9];
  float* out = (float*)d_out;

  int B = in_sizes[1] / DIMH;   // 4096

  prep_kernel<<<16, THREADS>>>(W1u, b1u, W2u, b2u, W1p, b1p, W2p, b2p);
  fem_main<<<B / ROWS, THREADS>>>(u, h, out);   // 512 blocks, tiny smem
}

// round 5
// speedup vs baseline: 1.0832x; 1.0832x over previous
#include <cuda_runtime.h>
#include <cstdint>
#include <cstddef>

#define HID     64
#define DIMH    128
#define DIMU    256
#define BATCH   4096
#define KSPLIT  4
#define KCH     (DIMH / KSPLIT)     // 32 k per split
#define ROWS1   16                  // rows per K1 CTA
#define WPAD1   36                  // floats per smem row in K1 (32 + 4 pad)

// ---------- persistent device scratch ----------
__device__ float  g_Wpack[128 * 128];        // rows 0..63: W1u[:,1:], 64..127: W1p[:,2:]
__device__ float  g_par[7 * 64 + 2];
// par: [0,64) cu | [64,128) cp0 | [128,192) cp1 | [192,256) b1u
//      [256,320) b1p | [320,384) W2u | [384,448) W2p | [448] b2u | [449] b2p
__device__ float  g_base[KSPLIT][BATCH * 128];   // partial pre-activations (8 MB)
__device__ float4 g_counts[BATCH];               // {n1, c01, c10, c11}

__device__ __forceinline__ float gelu_f(float x) {
  return 0.5f * x * (1.0f + erff(x * 0.7071067811865476f));
}

// ---------- prep: repack W + params into aligned layout ----------
__global__ void __launch_bounds__(128) prep_kernel(
    const float* __restrict__ W1u, const float* __restrict__ b1u,
    const float* __restrict__ W2u, const float* __restrict__ b2u,
    const float* __restrict__ W1p, const float* __restrict__ b1p,
    const float* __restrict__ W2p, const float* __restrict__ b2p)
{
  int t = threadIdx.x;          // k column 0..127
  int b = blockIdx.x;           // 16 blocks x 8 rows
#pragma unroll
  for (int rr = 0; rr < 8; rr++) {
    int r = b * 8 + rr;
    float v = (r < HID) ? W1u[r * 129 + 1 + t]
                        : W1p[(r - HID) * 130 + 2 + t];
    g_Wpack[r * 128 + t] = v;
  }
  if (b == 0 && t < HID) {
    g_par[t]       = W1u[t * 129];
    g_par[64 + t]  = W1p[t * 130];
    g_par[128 + t] = W1p[t * 130 + 1];
    g_par[192 + t] = b1u[t];
    g_par[256 + t] = b1p[t];
    g_par[320 + t] = W2u[t];
    g_par[384 + t] = W2p[t];
    if (t == 0) { g_par[448] = b2u[0]; g_par[449] = b2p[0]; }
  }
}

// ---------- K1: k-split GEMM (+ u-counting on kh==0 slices) ----------
__global__ void __launch_bounds__(128, 6) k1_gemm(
    const float* __restrict__ u, const float* __restrict__ h)
{
  __shared__ float Ws[128][WPAD1];   // W slice [128 j][32 k]
  __shared__ float hs[ROWS1][WPAD1]; // h slice [16 rows][32 k]

  const int tid  = threadIdx.x;
  const int lane = tid & 31;
  const int w    = tid >> 5;
  const int r0   = blockIdx.x * ROWS1;
  const int kh   = blockIdx.y;

  // stage W slice: 128 x 32 floats = 1024 float4
  {
    const float4* W4 = reinterpret_cast<const float4*>(g_Wpack);
#pragma unroll
    for (int it = 0; it < 8; it++) {
      int i = tid + it * 128;              // 0..1023
      int j = i >> 3, c4 = i & 7;
      float4 v = W4[j * 32 + kh * 8 + c4];
      *reinterpret_cast<float4*>(&Ws[j][c4 * 4]) = v;
    }
  }
  // stage h slice: 16 x 32 floats = 128 float4
  {
    const float4* h4 = reinterpret_cast<const float4*>(h);
    int row = tid >> 3, c4 = tid & 7;
    float4 v = h4[(size_t)(r0 + row) * 32 + kh * 8 + c4];
    *reinterpret_cast<float4*>(&hs[row][c4 * 4]) = v;
  }

  // u-counting (only kh==0 slices): warp w counts rows 4w..4w+3
  if (kh == 0) {
    const float4* u4 = reinterpret_cast<const float4*>(u);
#pragma unroll
    for (int t2 = 0; t2 < 4; t2++) {
      int rr = w * 4 + t2;
      size_t base = (size_t)(r0 + rr) * (DIMU / 4);
      float4 a = u4[base + lane];
      float4 b = u4[base + 32 + lane];
      int a0 = a.x > 0.5f, a1 = a.y > 0.5f, a2 = a.z > 0.5f, a3 = a.w > 0.5f;
      int e0 = b.x > 0.5f, e1 = b.y > 0.5f, e2 = b.z > 0.5f, e3 = b.w > 0.5f;
      int n1 = a0 + a1 + a2 + a3 + e0 + e1 + e2 + e3;
      const unsigned F = 0xffffffffu;
      int a0n  = __shfl_down_sync(F, a0, 1);
      int e0n  = __shfl_down_sync(F, e0, 1);
      int e0l0 = __shfl_sync(F, e0, 0);
      int c11 = 0, c10 = 0, c01 = 0;
#define ADDP(X, Y) { c11 += (X) & (Y); c10 += (X) & (1 ^ (Y)); c01 += (1 ^ (X)) & (Y); }
      ADDP(a0, a1) ADDP(a1, a2) ADDP(a2, a3)
      int xa = (lane < 31) ? a0n : e0l0;
      ADDP(a3, xa)
      ADDP(e0, e1) ADDP(e1, e2) ADDP(e2, e3)
      if (lane < 31) ADDP(e3, e0n)
#undef ADDP
      n1  = __reduce_add_sync(F, n1);
      c11 = __reduce_add_sync(F, c11);
      c10 = __reduce_add_sync(F, c10);
      c01 = __reduce_add_sync(F, c01);
      if (lane == 0)
        g_counts[r0 + rr] = make_float4((float)n1, (float)c01, (float)c10, (float)c11);
    }
  }
  __syncthreads();

  // GEMM: thread = (row = tid>>3, jg = tid&7), j-set = {jg + 8*jj}.
  // LDS banks: W row stride 36 floats -> jg spans banks {4jg..4jg+3}: all 32,
  // 4 row-replica lanes broadcast. h: rows span {4row..}, jg broadcast.
  const int row = tid >> 3;
  const int jg  = tid & 7;
  unsigned long long acc2[16];
#pragma unroll
  for (int jj = 0; jj < 16; jj++) acc2[jj] = 0ull;
  const float* hrow = &hs[row][0];
  const float* wcol = &Ws[jg][0];
#pragma unroll
  for (int kq = 0; kq < KCH / 4; kq++) {
    ulonglong2 hv = *reinterpret_cast<const ulonglong2*>(hrow + kq * 4);
#pragma unroll
    for (int jj = 0; jj < 16; jj++) {
      ulonglong2 wv = *reinterpret_cast<const ulonglong2*>(wcol + jj * 8 * WPAD1 + kq * 4);
      asm("fma.rn.f32x2 %0, %1, %2, %0;" : "+l"(acc2[jj]) : "l"(hv.x), "l"(wv.x));
      asm("fma.rn.f32x2 %0, %1, %2, %0;" : "+l"(acc2[jj]) : "l"(hv.y), "l"(wv.y));
    }
  }

  float* dst = g_base[kh] + (size_t)(r0 + row) * 128;
#pragma unroll
  for (int jj = 0; jj < 16; jj++) {
    float lo, hi;
    asm("mov.b64 {%0, %1}, %2;" : "=f"(lo), "=f"(hi) : "l"(acc2[jj]));
    dst[jg + 8 * jj] = lo + hi;
  }
}

// ---------- K2: gelu epilogue + count-weighted reduce ----------
__global__ void __launch_bounds__(256, 4) k2_epi(float* __restrict__ out)
{
  __shared__ float part[2][8];

  const int tid  = threadIdx.x;
  const int half = tid >> 7;          // 0: unary (warps 0-3), 1: pairwise (4-7)
  const int t    = tid & 127;
  const int row  = t >> 4;            // 8 rows per CTA
  const int jg   = t & 15;            // 16 jgroups x 4 j
  const int gr   = blockIdx.x * 8 + row;

  const int j0 = (half == 0) ? jg * 4 : 64 + jg * 4;
  float b0 = 0.f, b1v = 0.f, b2v = 0.f, b3v = 0.f;
#pragma unroll
  for (int kh = 0; kh < KSPLIT; kh++) {
    float4 v = *reinterpret_cast<const float4*>(g_base[kh] + (size_t)gr * 128 + j0);
    b0 += v.x; b1v += v.y; b2v += v.z; b3v += v.w;
  }
  float bb[4] = {b0, b1v, b2v, b3v};

  float4 cnt = g_counts[gr];
  float val;
  if (half == 0) {
    float g0 = 0.f, g1 = 0.f;
#pragma unroll
    for (int i = 0; i < 4; i++) {
      int j = j0 + i;
      float base = bb[i] + g_par[192 + j];
      float w2 = g_par[320 + j];
      g0 += w2 * gelu_f(base);
      g1 += w2 * gelu_f(base + g_par[j]);
    }
    val = (256.0f - cnt.x) * g0 + cnt.x * g1;
  } else {
    float p00 = 0.f, p01 = 0.f, p10 = 0.f, p11 = 0.f;
#pragma unroll
    for (int i = 0; i < 4; i++) {
      int jp = j0 - 64 + i;
      float base = bb[i] + g_par[256 + jp];
      float A  = g_par[64 + jp];
      float Bv = g_par[128 + jp];
      float w2 = g_par[384 + jp];
      p00 += w2 * gelu_f(base);
      p01 += w2 * gelu_f(base + Bv);
      p10 += w2 * gelu_f(base + A);
      p11 += w2 * gelu_f(base + A + Bv);
    }
    float c00 = 255.0f - cnt.y - cnt.z - cnt.w;
    val = c00 * p00 + cnt.y * p01 + cnt.z * p10 + cnt.w * p11;
  }

  // butterfly over the 16 jg lanes (stays within half-warp groups)
  const unsigned F = 0xffffffffu;
  val += __shfl_xor_sync(F, val, 1);
  val += __shfl_xor_sync(F, val, 2);
  val += __shfl_xor_sync(F, val, 4);
  val += __shfl_xor_sync(F, val, 8);
  if (jg == 0) part[half][row] = val;
  __syncthreads();

  if (tid < 8)
    out[blockIdx.x * 8 + tid] =
        part[0][tid] + part[1][tid] + 256.0f * g_par[448] + 255.0f * g_par[449];
}

extern "C" void kernel_launch(void* const* d_in, const int* in_sizes, int n_in,
                              void* d_out, int out_size) {
  const float* u   = (const float*)d_in[0];
  const float* h   = (const float*)d_in[1];
  const float* W1u = (const float*)d_in[2];
  const float* b1u = (const float*)d_in[3];
  const float* W2u = (const float*)d_in[4];
  const float* b2u = (const float*)d_in[5];
  const float* W1p = (const float*)d_in[6];
  const float* b1p = (const float*)d_in[7];
  const float* W2p = (const float*)d_in[8];
  const float* b2p = (const float*)d_in[9];
  float* out = (float*)d_out;

  prep_kernel<<<16, 128>>>(W1u, b1u, W2u, b2u, W1p, b1p, W2p, b2p);
  dim3 g1(BATCH / ROWS1, KSPLIT);                  // (256, 4)
  k1_gemm<<<g1, 128>>>(u, h);
  k2_epi<<<BATCH / 8, 256>>>(out);
}

// round 6
// speedup vs baseline: 1.0894x; 1.0057x over previous
#include <cuda_runtime.h>
#include <cstdint>
#include <cstddef>

#define HID     64
#define DIMH    128
#define DIMU    256
#define BATCH   4096
#define KSPLIT  4
#define KCH     (DIMH / KSPLIT)     // 32 k per split
#define ROWS1   16                  // rows per K1 CTA
#define WPAD1   36                  // floats per smem row in K1 (32 + 4 pad)

// ---------- persistent device scratch ----------
__device__ float  g_Wpack[128 * 128];        // rows 0..63: W1u[:,1:], 64..127: W1p[:,2:]
__device__ float  g_par[7 * 64 + 2];
// par: [0,64) cu | [64,128) cp0 | [128,192) cp1 | [192,256) b1u
//      [256,320) b1p | [320,384) W2u | [384,448) W2p | [448] b2u | [449] b2p
__device__ float  g_base[KSPLIT][BATCH * 128];   // partial pre-activations (8 MB)
__device__ float4 g_counts[BATCH];               // {n1, c01, c10, c11}

__device__ __forceinline__ float gelu_f(float x) {
  return 0.5f * x * (1.0f + erff(x * 0.7071067811865476f));
}

// ---------- prep: repack W + params into aligned layout ----------
__global__ void __launch_bounds__(128) prep_kernel(
    const float* __restrict__ W1u, const float* __restrict__ b1u,
    const float* __restrict__ W2u, const float* __restrict__ b2u,
    const float* __restrict__ W1p, const float* __restrict__ b1p,
    const float* __restrict__ W2p, const float* __restrict__ b2p)
{
  int t = threadIdx.x;          // k column 0..127
  int b = blockIdx.x;           // 16 blocks x 8 rows
#pragma unroll
  for (int rr = 0; rr < 8; rr++) {
    int r = b * 8 + rr;
    float v = (r < HID) ? W1u[r * 129 + 1 + t]
                        : W1p[(r - HID) * 130 + 2 + t];
    g_Wpack[r * 128 + t] = v;
  }
  if (b == 0 && t < HID) {
    g_par[t]       = W1u[t * 129];
    g_par[64 + t]  = W1p[t * 130];
    g_par[128 + t] = W1p[t * 130 + 1];
    g_par[192 + t] = b1u[t];
    g_par[256 + t] = b1p[t];
    g_par[320 + t] = W2u[t];
    g_par[384 + t] = W2p[t];
    if (t == 0) { g_par[448] = b2u[0]; g_par[449] = b2p[0]; }
  }
}

// ---------- K1: k-split GEMM (+ u-counting on kh==0 slices) ----------
__global__ void __launch_bounds__(128, 6) k1_gemm(
    const float* __restrict__ u, const float* __restrict__ h)
{
  __shared__ float Ws[128][WPAD1];   // W slice [128 j][32 k]
  __shared__ float hs[ROWS1][WPAD1]; // h slice [16 rows][32 k]

  const int tid  = threadIdx.x;
  const int lane = tid & 31;
  const int w    = tid >> 5;
  const int r0   = blockIdx.x * ROWS1;
  const int kh   = blockIdx.y;

  // stage W slice: 128 x 32 floats = 1024 float4
  {
    const float4* W4 = reinterpret_cast<const float4*>(g_Wpack);
#pragma unroll
    for (int it = 0; it < 8; it++) {
      int i = tid + it * 128;              // 0..1023
      int j = i >> 3, c4 = i & 7;
      float4 v = W4[j * 32 + kh * 8 + c4];
      *reinterpret_cast<float4*>(&Ws[j][c4 * 4]) = v;
    }
  }
  // stage h slice: 16 x 32 floats = 128 float4
  {
    const float4* h4 = reinterpret_cast<const float4*>(h);
    int row = tid >> 3, c4 = tid & 7;
    float4 v = h4[(size_t)(r0 + row) * 32 + kh * 8 + c4];
    *reinterpret_cast<float4*>(&hs[row][c4 * 4]) = v;
  }

  // u-counting (only kh==0 slices): warp w counts rows 4w..4w+3
  if (kh == 0) {
    const float4* u4 = reinterpret_cast<const float4*>(u);
#pragma unroll
    for (int t2 = 0; t2 < 4; t2++) {
      int rr = w * 4 + t2;
      size_t base = (size_t)(r0 + rr) * (DIMU / 4);
      float4 a = u4[base + lane];
      float4 b = u4[base + 32 + lane];
      int a0 = a.x > 0.5f, a1 = a.y > 0.5f, a2 = a.z > 0.5f, a3 = a.w > 0.5f;
      int e0 = b.x > 0.5f, e1 = b.y > 0.5f, e2 = b.z > 0.5f, e3 = b.w > 0.5f;
      int n1 = a0 + a1 + a2 + a3 + e0 + e1 + e2 + e3;
      const unsigned F = 0xffffffffu;
      int a0n  = __shfl_down_sync(F, a0, 1);
      int e0n  = __shfl_down_sync(F, e0, 1);
      int e0l0 = __shfl_sync(F, e0, 0);
      int c11 = 0, c10 = 0, c01 = 0;
#define ADDP(X, Y) { c11 += (X) & (Y); c10 += (X) & (1 ^ (Y)); c01 += (1 ^ (X)) & (Y); }
      ADDP(a0, a1) ADDP(a1, a2) ADDP(a2, a3)
      int xa = (lane < 31) ? a0n : e0l0;
      ADDP(a3, xa)
      ADDP(e0, e1) ADDP(e1, e2) ADDP(e2, e3)
      if (lane < 31) ADDP(e3, e0n)
#undef ADDP
      n1  = __reduce_add_sync(F, n1);
      c11 = __reduce_add_sync(F, c11);
      c10 = __reduce_add_sync(F, c10);
      c01 = __reduce_add_sync(F, c01);
      if (lane == 0)
        g_counts[r0 + rr] = make_float4((float)n1, (float)c01, (float)c10, (float)c11);
    }
  }
  __syncthreads();

  // GEMM: thread = (row = tid>>3, jg = tid&7), j-set = {jg + 8*jj}.
  // LDS banks: W row stride 36 floats -> jg spans banks {4jg..4jg+3}: all 32,
  // 4 row-replica lanes broadcast. h: rows span {4row..}, jg broadcast.
  const int row = tid >> 3;
  const int jg  = tid & 7;
  unsigned long long acc2[16];
#pragma unroll
  for (int jj = 0; jj < 16; jj++) acc2[jj] = 0ull;
  const float* hrow = &hs[row][0];
  const float* wcol = &Ws[jg][0];
#pragma unroll
  for (int kq = 0; kq < KCH / 4; kq++) {
    ulonglong2 hv = *reinterpret_cast<const ulonglong2*>(hrow + kq * 4);
#pragma unroll
    for (int jj = 0; jj < 16; jj++) {
      ulonglong2 wv = *reinterpret_cast<const ulonglong2*>(wcol + jj * 8 * WPAD1 + kq * 4);
      asm("fma.rn.f32x2 %0, %1, %2, %0;" : "+l"(acc2[jj]) : "l"(hv.x), "l"(wv.x));
      asm("fma.rn.f32x2 %0, %1, %2, %0;" : "+l"(acc2[jj]) : "l"(hv.y), "l"(wv.y));
    }
  }

  float* dst = g_base[kh] + (size_t)(r0 + row) * 128;
#pragma unroll
  for (int jj = 0; jj < 16; jj++) {
    float lo, hi;
    asm("mov.b64 {%0, %1}, %2;" : "=f"(lo), "=f"(hi) : "l"(acc2[jj]));
    dst[jg + 8 * jj] = lo + hi;
  }
}

// ---------- K2: gelu epilogue + count-weighted reduce ----------
__global__ void __launch_bounds__(256, 4) k2_epi(float* __restrict__ out)
{
  __shared__ float part[2][8];

  const int tid  = threadIdx.x;
  const int half = tid >> 7;          // 0: unary (warps 0-3), 1: pairwise (4-7)
  const int t    = tid & 127;
  const int row  = t >> 4;            // 8 rows per CTA
  const int jg   = t & 15;            // 16 jgroups x 4 j
  const int gr   = blockIdx.x * 8 + row;

  const int j0 = (half == 0) ? jg * 4 : 64 + jg * 4;
  float b0 = 0.f, b1v = 0.f, b2v = 0.f, b3v = 0.f;
#pragma unroll
  for (int kh = 0; kh < KSPLIT; kh++) {
    float4 v = *reinterpret_cast<const float4*>(g_base[kh] + (size_t)gr * 128 + j0);
    b0 += v.x; b1v += v.y; b2v += v.z; b3v += v.w;
  }
  float bb[4] = {b0, b1v, b2v, b3v};

  float4 cnt = g_counts[gr];
  float val;
  if (half == 0) {
    float g0 = 0.f, g1 = 0.f;
#pragma unroll
    for (int i = 0; i < 4; i++) {
      int j = j0 + i;
      float base = bb[i] + g_par[192 + j];
      float w2 = g_par[320 + j];
      g0 += w2 * gelu_f(base);
      g1 += w2 * gelu_f(base + g_par[j]);
    }
    val = (256.0f - cnt.x) * g0 + cnt.x * g1;
  } else {
    float p00 = 0.f, p01 = 0.f, p10 = 0.f, p11 = 0.f;
#pragma unroll
    for (int i = 0; i < 4; i++) {
      int jp = j0 - 64 + i;
      float base = bb[i] + g_par[256 + jp];
      float A  = g_par[64 + jp];
      float Bv = g_par[128 + jp];
      float w2 = g_par[384 + jp];
      p00 += w2 * gelu_f(base);
      p01 += w2 * gelu_f(base + Bv);
      p10 += w2 * gelu_f(base + A);
      p11 += w2 * gelu_f(base + A + Bv);
    }
    float c00 = 255.0f - cnt.y - cnt.z - cnt.w;
    val = c00 * p00 + cnt.y * p01 + cnt.z * p10 + cnt.w * p11;
  }

  // butterfly over the 16 jg lanes (stays within half-warp groups)
  const unsigned F = 0xffffffffu;
  val += __shfl_xor_sync(F, val, 1);
  val += __shfl_xor_sync(F, val, 2);
  val += __shfl_xor_sync(F, val, 4);
  val += __shfl_xor_sync(F, val, 8);
  if (jg == 0) part[half][row] = val;
  __syncthreads();

  if (tid < 8)
    out[blockIdx.x * 8 + tid] =
        part[0][tid] + part[1][tid] + 256.0f * g_par[448] + 255.0f * g_par[449];
}

extern "C" void kernel_launch(void* const* d_in, const int* in_sizes, int n_in,
                              void* d_out, int out_size) {
  const float* u   = (const float*)d_in[0];
  const float* h   = (const float*)d_in[1];
  const float* W1u = (const float*)d_in[2];
  const float* b1u = (const float*)d_in[3];
  const float* W2u = (const float*)d_in[4];
  const float* b2u = (const float*)d_in[5];
  const float* W1p = (const float*)d_in[6];
  const float* b1p = (const float*)d_in[7];
  const float* W2p = (const float*)d_in[8];
  const float* b2p = (const float*)d_in[9];
  float* out = (float*)d_out;

  prep_kernel<<<16, 128>>>(W1u, b1u, W2u, b2u, W1p, b1p, W2p, b2p);
  dim3 g1(BATCH / ROWS1, KSPLIT);                  // (256, 4)
  k1_gemm<<<g1, 128>>>(u, h);
  k2_epi<<<BATCH / 8, 256>>>(out);
}

// round 7
// speedup vs baseline: 1.6445x; 1.5096x over previous
#include <cuda_runtime.h>
#include <cstdint>
#include <cstddef>

#define HID     64
#define DIMH    128
#define DIMU    256
#define ROWS    16
#define NWARP   8
#define THREADS 256
#define JPW     8
#define HPAD    132

// smem layout (float offsets)
#define OFF_W    0                       // Wc[128][128]: rows 0..63 unary W, 64..127 pairwise W
#define OFF_H    16384                   // hs[16][132]
#define OFF_PAR  (OFF_H + ROWS * HPAD)   // cu|cp0|cp1|b1u|b1p|W2u|W2p (7*64) + b2u,b2p
#define OFF_CNT  (OFF_PAR + 452)         // float4[16]; 18948 -> byte offset 16B aligned
#define OFF_PART (OFF_CNT + 4 * ROWS)    // partial[16][16]
#define SMEM_FLOATS (OFF_PART + 16 * ROWS)
#define SMEM_BYTES  (SMEM_FLOATS * 4)

#define P_CU  0
#define P_CP0 64
#define P_CP1 128
#define P_B1U 192
#define P_B1P 256
#define P_W2U 320
#define P_W2P 384
#define P_B2  448

__device__ __forceinline__ float gelu_f(float x) {
  return 0.5f * x * (1.0f + erff(x * 0.7071067811865476f));
}

__device__ __forceinline__ void cp16(uint32_t dst, const void* src) {
  asm volatile("cp.async.cg.shared.global [%0], [%1], 16;" :: "r"(dst), "l"(src));
}
__device__ __forceinline__ void cp4(uint32_t dst, const void* src) {
  asm volatile("cp.async.ca.shared.global [%0], [%1], 4;" :: "r"(dst), "l"(src));
}

extern __shared__ __align__(16) float sm[];

__global__ void __launch_bounds__(THREADS) fem_kernel(
    const float* __restrict__ u,   const float* __restrict__ h,
    const float* __restrict__ W1u, const float* __restrict__ b1u,
    const float* __restrict__ W2u, const float* __restrict__ b2u,
    const float* __restrict__ W1p, const float* __restrict__ b1p,
    const float* __restrict__ W2p, const float* __restrict__ b2p,
    float* __restrict__ out)
{
  const int tid  = threadIdx.x;
  const int lane = tid & 31;
  const int w    = tid >> 5;
  const int r0   = blockIdx.x * ROWS;
  const uint32_t smb = (uint32_t)__cvta_generic_to_shared(sm);

  // ---- async staging: W repacked aligned via 4B cp.async (no div/mod) ----
  {
    const int k  = tid & 127;          // constant per thread
    const int j0 = tid >> 7;           // 0 or 1
    const float* srcU = W1u + (size_t)j0 * 129 + 1 + k;
    const float* srcP = W1p + (size_t)j0 * 130 + 2 + k;
    uint32_t dstU = smb + (uint32_t)(OFF_W + j0 * 128 + k) * 4;
    uint32_t dstP = dstU + 64 * 128 * 4;
#pragma unroll
    for (int it = 0; it < 32; it++) {          // j = j0 + 2*it covers 0..63
      cp4(dstU, srcU);  srcU += 2 * 129;  dstU += 2 * 128 * 4;
      cp4(dstP, srcP);  srcP += 2 * 130;  dstP += 2 * 128 * 4;
    }
  }
  // params: threads 0..63 each stage 7 scalars for j=tid
  if (tid < HID) {
    uint32_t pb = smb + OFF_PAR * 4;
    cp4(pb + (P_CU  + tid) * 4, W1u + (size_t)tid * 129);
    cp4(pb + (P_CP0 + tid) * 4, W1p + (size_t)tid * 130);
    cp4(pb + (P_CP1 + tid) * 4, W1p + (size_t)tid * 130 + 1);
    cp4(pb + (P_B1U + tid) * 4, b1u + tid);
    cp4(pb + (P_B1P + tid) * 4, b1p + tid);
    cp4(pb + (P_W2U + tid) * 4, W2u + tid);
    cp4(pb + (P_W2P + tid) * 4, W2p + tid);
    if (tid == 0) { cp4(pb + P_B2 * 4, b2u); cp4(pb + (P_B2 + 1) * 4, b2p); }
  }
  // h tile [16 x 128] via 16B cp.async
  {
    const float4* h4 = reinterpret_cast<const float4*>(h) + (size_t)r0 * (DIMH / 4);
#pragma unroll
    for (int it = 0; it < 2; it++) {
      int i = tid + it * THREADS;              // 0..511
      int row = i >> 5, c4 = i & 31;
      cp16(smb + (OFF_H + row * HPAD + c4 * 4) * 4, h4 + i);
    }
  }
  asm volatile("cp.async.commit_group;" ::: "memory");

  // ---- u-counting overlapped with cp.async drain ----
  {
    const float4* u4 = reinterpret_cast<const float4*>(u);
#pragma unroll
    for (int t2 = 0; t2 < 2; t2++) {
      int rr = w + t2 * NWARP;
      size_t base = (size_t)(r0 + rr) * (DIMU / 4);
      float4 a = u4[base + lane];
      float4 b = u4[base + 32 + lane];
      int a0 = a.x > 0.5f, a1 = a.y > 0.5f, a2 = a.z > 0.5f, a3 = a.w > 0.5f;
      int e0 = b.x > 0.5f, e1 = b.y > 0.5f, e2 = b.z > 0.5f, e3 = b.w > 0.5f;
      int n1 = a0 + a1 + a2 + a3 + e0 + e1 + e2 + e3;
      const unsigned F = 0xffffffffu;
      int a0n  = __shfl_down_sync(F, a0, 1);
      int e0n  = __shfl_down_sync(F, e0, 1);
      int e0l0 = __shfl_sync(F, e0, 0);
      int c11 = 0, c10 = 0, c01 = 0;
#define ADDP(X, Y) { c11 += (X) & (Y); c10 += (X) & (1 ^ (Y)); c01 += (1 ^ (X)) & (Y); }
      ADDP(a0, a1) ADDP(a1, a2) ADDP(a2, a3)
      int xa = (lane < 31) ? a0n : e0l0;
      ADDP(a3, xa)
      ADDP(e0, e1) ADDP(e1, e2) ADDP(e2, e3)
      if (lane < 31) ADDP(e3, e0n)
#undef ADDP
      n1  = __reduce_add_sync(F, n1);
      c11 = __reduce_add_sync(F, c11);
      c10 = __reduce_add_sync(F, c10);
      c01 = __reduce_add_sync(F, c01);
      if (lane == 0)
        *reinterpret_cast<float4*>(sm + OFF_CNT + 4 * rr) =
            make_float4((float)n1, (float)c01, (float)c10, (float)c11);
    }
  }

  asm volatile("cp.async.wait_group 0;" ::: "memory");
  __syncthreads();

  // ---- fused GEMM (validated r3 mapping) ----
  // row = lane&15; jgroup g = 2w + (lane>>4); 16 groups x 8 j.
  // W reads: half-warp-uniform broadcast (stride 128, no pad needed).
  // h reads: HPAD=132 -> 8-lane wavefronts cover all 32 banks.
  const int row   = lane & 15;
  const int g     = (w << 1) + (lane >> 4);
  const int jbase = g * JPW;
  unsigned long long acc2[JPW];
#pragma unroll
  for (int jj = 0; jj < JPW; jj++) acc2[jj] = 0ull;
  const float* hrow = sm + OFF_H + row * HPAD;
  const float* wrow = sm + OFF_W + jbase * 128;
#pragma unroll 2
  for (int k = 0; k < DIMH; k += 4) {
    ulonglong2 hv = *reinterpret_cast<const ulonglong2*>(hrow + k);
#pragma unroll
    for (int jj = 0; jj < JPW; jj++) {
      ulonglong2 wv = *reinterpret_cast<const ulonglong2*>(wrow + jj * 128 + k);
      asm("fma.rn.f32x2 %0, %1, %2, %0;" : "+l"(acc2[jj]) : "l"(hv.x), "l"(wv.x));
      asm("fma.rn.f32x2 %0, %1, %2, %0;" : "+l"(acc2[jj]) : "l"(hv.y), "l"(wv.y));
    }
  }

  // ---- epilogue: binary-u collapse ----
  const float* par = sm + OFF_PAR;
  float4 cnt = *reinterpret_cast<const float4*>(sm + OFF_CNT + 4 * row);
  float val;
  if (w < NWARP / 2) {                  // unary: g 0..7, j = jbase+jj
    float g0 = 0.f, g1 = 0.f;
#pragma unroll
    for (int jj = 0; jj < JPW; jj++) {
      int j = jbase + jj;
      float lo, hi;
      asm("mov.b64 {%0, %1}, %2;" : "=f"(lo), "=f"(hi) : "l"(acc2[jj]));
      float base = lo + hi + par[P_B1U + j];
      float w2 = par[P_W2U + j];
      g0 += w2 * gelu_f(base);
      g1 += w2 * gelu_f(base + par[P_CU + j]);
    }
    val = (256.0f - cnt.x) * g0 + cnt.x * g1;
  } else {                              // pairwise: g 8..15, j = jbase-64+jj
    float p00 = 0.f, p01 = 0.f, p10 = 0.f, p11 = 0.f;
#pragma unroll
    for (int jj = 0; jj < JPW; jj++) {
      int j = jbase - HID + jj;
      float lo, hi;
      asm("mov.b64 {%0, %1}, %2;" : "=f"(lo), "=f"(hi) : "l"(acc2[jj]));
      float base = lo + hi + par[P_B1P + j];
      float A  = par[P_CP0 + j];
      float Bv = par[P_CP1 + j];
      float w2 = par[P_W2P + j];
      p00 += w2 * gelu_f(base);
      p01 += w2 * gelu_f(base + Bv);
      p10 += w2 * gelu_f(base + A);
      p11 += w2 * gelu_f(base + A + Bv);
    }
    float c00 = 255.0f - cnt.y - cnt.z - cnt.w;
    val = c00 * p00 + cnt.y * p01 + cnt.z * p10 + cnt.w * p11;
  }
  sm[OFF_PART + g * ROWS + row] = val;
  __syncthreads();

  if (tid < ROWS) {
    float e = 0.f;
#pragma unroll
    for (int gg = 0; gg < 16; gg++) e += sm[OFF_PART + gg * ROWS + tid];
    e += 256.0f * par[P_B2] + 255.0f * par[P_B2 + 1];
    out[r0 + tid] = e;
  }
}

extern "C" void kernel_launch(void* const* d_in, const int* in_sizes, int n_in,
                              void* d_out, int out_size) {
  const float* u   = (const float*)d_in[0];
  const float* h   = (const float*)d_in[1];
  const float* W1u = (const float*)d_in[2];
  const float* b1u = (const float*)d_in[3];
  const float* W2u = (const float*)d_in[4];
  const float* b2u = (const float*)d_in[5];
  const float* W1p = (const float*)d_in[6];
  const float* b1p = (const float*)d_in[7];
  const float* W2p = (const float*)d_in[8];
  const float* b2p = (const float*)d_in[9];
  float* out = (float*)d_out;

  int B = in_sizes[1] / DIMH;   // 4096
  cudaFuncSetAttribute(fem_kernel, cudaFuncAttributeMaxDynamicSharedMemorySize, SMEM_BYTES);
  fem_kernel<<<B / ROWS, THREADS, SMEM_BYTES>>>(
      u, h, W1u, b1u, W2u, b2u, W1p, b1p, W2p, b2p, out);
}

// round 8
// speedup vs baseline: 1.6991x; 1.0332x over previous
#include <cuda_runtime.h>
#include <cstdint>
#include <cstddef>

#define HID     64
#define DIMH    128
#define DIMU    256
#define ROWS    16
#define NWARP   8
#define THREADS 256
#define JPW     8
#define HPAD    132

// smem layout (float offsets)
#define OFF_W    0                       // Wc[128][128]: rows 0..63 unary W, 64..127 pairwise W
#define OFF_H    16384                   // hs[16][132]
#define OFF_PAR  (OFF_H + ROWS * HPAD)   // cu|cp0|cp1|b1u|b1p|W2u|W2p (7*64) + b2u,b2p
#define OFF_CNT  (OFF_PAR + 452)         // float4[16]
#define OFF_PART (OFF_CNT + 4 * ROWS)    // partial[16][16]
#define SMEM_FLOATS (OFF_PART + 16 * ROWS)
#define SMEM_BYTES  (SMEM_FLOATS * 4)

#define P_CU  0
#define P_CP0 64
#define P_CP1 128
#define P_B1U 192
#define P_B1P 256
#define P_W2U 320
#define P_W2P 384
#define P_B2  448

__device__ __forceinline__ float gelu_f(float x) {
  return 0.5f * x * (1.0f + erff(x * 0.7071067811865476f));
}

__device__ __forceinline__ void cp16(uint32_t dst, const void* src) {
  asm volatile("cp.async.cg.shared.global [%0], [%1], 16;" :: "r"(dst), "l"(src));
}
__device__ __forceinline__ void cp4(uint32_t dst, const void* src) {
  asm volatile("cp.async.ca.shared.global [%0], [%1], 4;" :: "r"(dst), "l"(src));
}

extern __shared__ __align__(16) float sm[];

__global__ void __launch_bounds__(THREADS, 2) fem_kernel(
    const float* __restrict__ u,   const float* __restrict__ h,
    const float* __restrict__ W1u, const float* __restrict__ b1u,
    const float* __restrict__ W2u, const float* __restrict__ b2u,
    const float* __restrict__ W1p, const float* __restrict__ b1p,
    const float* __restrict__ W2p, const float* __restrict__ b2p,
    float* __restrict__ out)
{
  const int tid  = threadIdx.x;
  const int lane = tid & 31;
  const int w    = tid >> 5;
  const int r0   = blockIdx.x * ROWS;
  const uint32_t smb = (uint32_t)__cvta_generic_to_shared(sm);

  // ---- 0) issue u loads FIRST: their DRAM latency overlaps the staging burst ----
  float4 ua0, ub0, ua1, ub1;
  {
    const float4* u4 = reinterpret_cast<const float4*>(u);
    size_t base0 = (size_t)(r0 + w) * (DIMU / 4);
    size_t base1 = (size_t)(r0 + w + NWARP) * (DIMU / 4);
    ua0 = u4[base0 + lane];
    ub0 = u4[base0 + 32 + lane];
    ua1 = u4[base1 + lane];
    ub1 = u4[base1 + 32 + lane];
  }

  // ---- 1) async staging: W repacked aligned via 4B cp.async (no div/mod) ----
  {
    const int k  = tid & 127;          // constant per thread
    const int j0 = tid >> 7;           // 0 or 1
    const float* srcU = W1u + (size_t)j0 * 129 + 1 + k;
    const float* srcP = W1p + (size_t)j0 * 130 + 2 + k;
    uint32_t dstU = smb + (uint32_t)(OFF_W + j0 * 128 + k) * 4;
    uint32_t dstP = dstU + 64 * 128 * 4;
#pragma unroll
    for (int it = 0; it < 32; it++) {          // j = j0 + 2*it covers 0..63
      cp4(dstU, srcU);  srcU += 2 * 129;  dstU += 2 * 128 * 4;
      cp4(dstP, srcP);  srcP += 2 * 130;  dstP += 2 * 128 * 4;
    }
  }
  // params: threads 0..63 each stage 7 scalars for j=tid
  if (tid < HID) {
    uint32_t pb = smb + OFF_PAR * 4;
    cp4(pb + (P_CU  + tid) * 4, W1u + (size_t)tid * 129);
    cp4(pb + (P_CP0 + tid) * 4, W1p + (size_t)tid * 130);
    cp4(pb + (P_CP1 + tid) * 4, W1p + (size_t)tid * 130 + 1);
    cp4(pb + (P_B1U + tid) * 4, b1u + tid);
    cp4(pb + (P_B1P + tid) * 4, b1p + tid);
    cp4(pb + (P_W2U + tid) * 4, W2u + tid);
    cp4(pb + (P_W2P + tid) * 4, W2p + tid);
    if (tid == 0) { cp4(pb + P_B2 * 4, b2u); cp4(pb + (P_B2 + 1) * 4, b2p); }
  }
  // h tile [16 x 128] via 16B cp.async
  {
    const float4* h4 = reinterpret_cast<const float4*>(h) + (size_t)r0 * (DIMH / 4);
#pragma unroll
    for (int it = 0; it < 2; it++) {
      int i = tid + it * THREADS;              // 0..511
      int row = i >> 5, c4 = i & 31;
      cp16(smb + (OFF_H + row * HPAD + c4 * 4) * 4, h4 + i);
    }
  }
  asm volatile("cp.async.commit_group;" ::: "memory");

  // ---- 2) u-counting on pre-loaded registers (covers cp.async drain) ----
  {
#pragma unroll
    for (int t2 = 0; t2 < 2; t2++) {
      int rr = w + t2 * NWARP;
      float4 a = t2 ? ua1 : ua0;
      float4 b = t2 ? ub1 : ub0;
      int a0 = a.x > 0.5f, a1 = a.y > 0.5f, a2 = a.z > 0.5f, a3 = a.w > 0.5f;
      int e0 = b.x > 0.5f, e1 = b.y > 0.5f, e2 = b.z > 0.5f, e3 = b.w > 0.5f;
      int n1 = a0 + a1 + a2 + a3 + e0 + e1 + e2 + e3;
      const unsigned F = 0xffffffffu;
      int a0n  = __shfl_down_sync(F, a0, 1);
      int e0n  = __shfl_down_sync(F, e0, 1);
      int e0l0 = __shfl_sync(F, e0, 0);
      int c11 = 0, c10 = 0, c01 = 0;
#define ADDP(X, Y) { c11 += (X) & (Y); c10 += (X) & (1 ^ (Y)); c01 += (1 ^ (X)) & (Y); }
      ADDP(a0, a1) ADDP(a1, a2) ADDP(a2, a3)
      int xa = (lane < 31) ? a0n : e0l0;
      ADDP(a3, xa)
      ADDP(e0, e1) ADDP(e1, e2) ADDP(e2, e3)
      if (lane < 31) ADDP(e3, e0n)
#undef ADDP
      n1  = __reduce_add_sync(F, n1);
      c11 = __reduce_add_sync(F, c11);
      c10 = __reduce_add_sync(F, c10);
      c01 = __reduce_add_sync(F, c01);
      if (lane == 0)
        *reinterpret_cast<float4*>(sm + OFF_CNT + 4 * rr) =
            make_float4((float)n1, (float)c01, (float)c10, (float)c11);
    }
  }

  asm volatile("cp.async.wait_group 0;" ::: "memory");
  __syncthreads();

  // ---- 3) fused GEMM ----
  // row = lane&15; jgroup g = 2w + (lane>>4); 16 groups x 8 j.
  // W reads: half-warp-uniform broadcast. h reads: HPAD=132 conflict-free.
  const int row   = lane & 15;
  const int g     = (w << 1) + (lane >> 4);
  const int jbase = g * JPW;
  unsigned long long acc2[JPW];
#pragma unroll
  for (int jj = 0; jj < JPW; jj++) acc2[jj] = 0ull;
  const float* hrow = sm + OFF_H + row * HPAD;
  const float* wrow = sm + OFF_W + jbase * 128;
#pragma unroll 4
  for (int k = 0; k < DIMH; k += 4) {
    ulonglong2 hv = *reinterpret_cast<const ulonglong2*>(hrow + k);
#pragma unroll
    for (int jj = 0; jj < JPW; jj++) {
      ulonglong2 wv = *reinterpret_cast<const ulonglong2*>(wrow + jj * 128 + k);
      asm("fma.rn.f32x2 %0, %1, %2, %0;" : "+l"(acc2[jj]) : "l"(hv.x), "l"(wv.x));
      asm("fma.rn.f32x2 %0, %1, %2, %0;" : "+l"(acc2[jj]) : "l"(hv.y), "l"(wv.y));
    }
  }

  // ---- 4) epilogue: binary-u collapse ----
  const float* par = sm + OFF_PAR;
  float4 cnt = *reinterpret_cast<const float4*>(sm + OFF_CNT + 4 * row);
  float val;
  if (w < NWARP / 2) {                  // unary: g 0..7, j = jbase+jj
    float g0 = 0.f, g1 = 0.f;
#pragma unroll
    for (int jj = 0; jj < JPW; jj++) {
      int j = jbase + jj;
      float lo, hi;
      asm("mov.b64 {%0, %1}, %2;" : "=f"(lo), "=f"(hi) : "l"(acc2[jj]));
      float base = lo + hi + par[P_B1U + j];
      float w2 = par[P_W2U + j];
      g0 += w2 * gelu_f(base);
      g1 += w2 * gelu_f(base + par[P_CU + j]);
    }
    val = (256.0f - cnt.x) * g0 + cnt.x * g1;
  } else {                              // pairwise: g 8..15, j = jbase-64+jj
    float p00 = 0.f, p01 = 0.f, p10 = 0.f, p11 = 0.f;
#pragma unroll
    for (int jj = 0; jj < JPW; jj++) {
      int j = jbase - HID + jj;
      float lo, hi;
      asm("mov.b64 {%0, %1}, %2;" : "=f"(lo), "=f"(hi) : "l"(acc2[jj]));
      float base = lo + hi + par[P_B1P + j];
      float A  = par[P_CP0 + j];
      float Bv = par[P_CP1 + j];
      float w2 = par[P_W2P + j];
      p00 += w2 * gelu_f(base);
      p01 += w2 * gelu_f(base + Bv);
      p10 += w2 * gelu_f(base + A);
      p11 += w2 * gelu_f(base + A + Bv);
    }
    float c00 = 255.0f - cnt.y - cnt.z - cnt.w;
    val = c00 * p00 + cnt.y * p01 + cnt.z * p10 + cnt.w * p11;
  }
  sm[OFF_PART + g * ROWS + row] = val;
  __syncthreads();

  if (tid < ROWS) {
    float e = 0.f;
#pragma unroll
    for (int gg = 0; gg < 16; gg++) e += sm[OFF_PART + gg * ROWS + tid];
    e += 256.0f * par[P_B2] + 255.0f * par[P_B2 + 1];
    out[r0 + tid] = e;
  }
}

extern "C" void kernel_launch(void* const* d_in, const int* in_sizes, int n_in,
                              void* d_out, int out_size) {
  const float* u   = (const float*)d_in[0];
  const float* h   = (const float*)d_in[1];
  const float* W1u = (const float*)d_in[2];
  const float* b1u = (const float*)d_in[3];
  const float* W2u = (const float*)d_in[4];
  const float* b2u = (const float*)d_in[5];
  const float* W1p = (const float*)d_in[6];
  const float* b1p = (const float*)d_in[7];
  const float* W2p = (const float*)d_in[8];
  const float* b2p = (const float*)d_in[9];
  float* out = (float*)d_out;

  int B = in_sizes[1] / DIMH;   // 4096
  cudaFuncSetAttribute(fem_kernel, cudaFuncAttributeMaxDynamicSharedMemorySize, SMEM_BYTES);
  fem_kernel<<<B / ROWS, THREADS, SMEM_BYTES>>>(
      u, h, W1u, b1u, W2u, b2u, W1p, b1p, W2p, b2p, out);
}